// round 15
// baseline (speedup 1.0000x reference)
#include <cuda_runtime.h>
#include <cuda_fp16.h>
#include <cuda_bf16.h>
#include <cstdint>

// Problem constants (fixed by the reference: N=50000, K=32, FN=128, FE=64)
#define NMAX   50048          // 50000 padded to multiple of 128
#define FN     128
#define FE     64

// Scratch (device globals: allocation-free per harness rules)
__device__ float  g_Bt[192 * 128];        // B^T: row n<64: (wq@wk^T)[:,n]; row 64+j: wv[:,j]
__device__ float  g_q2[NMAX * 64];        // nodes @ (wq @ wk^T)   [N, FE] fp32
__device__ __half g_nv[NMAX * 128];       // nodes @ wv            [N, FN] fp16

// ---------------------------------------------------------------------------
// helpers
// ---------------------------------------------------------------------------
__device__ __forceinline__ void split2(float x, float y, uint32_t& hi, uint32_t& lo) {
    __nv_bfloat16 hx = __float2bfloat16_rn(x);
    __nv_bfloat16 hy = __float2bfloat16_rn(y);
    __nv_bfloat162 hh; hh.x = hx; hh.y = hy;
    hi = *(uint32_t*)&hh;
    __nv_bfloat162 ll = __floats2bfloat162_rn(x - __bfloat162float(hx),
                                              y - __bfloat162float(hy));
    lo = *(uint32_t*)&ll;
}

// mma.sync m16n8k16 bf16 (baseline PTX, sm_80+; compiles at compute_103)
#define MMA16816(d, a, b)                                                     \
    asm volatile(                                                             \
        "mma.sync.aligned.m16n8k16.row.col.f32.bf16.bf16.f32 "               \
        "{%0,%1,%2,%3}, {%4,%5,%6,%7}, {%8,%9}, {%0,%1,%2,%3};"              \
        : "+f"((d)[0]), "+f"((d)[1]), "+f"((d)[2]), "+f"((d)[3])              \
        : "r"((a)[0]), "r"((a)[1]), "r"((a)[2]), "r"((a)[3]),                 \
          "r"((b)[0]), "r"((b)[1]))

// cp.async (baseline PTX, sm_80+). .cg = L1-bypass 16B copy.
#define CP_ASYNC16(dst, src) \
    asm volatile("cp.async.cg.shared.global [%0], [%1], 16;" \
                 :: "r"(dst), "l"(src) : "memory")
#define CP_COMMIT() asm volatile("cp.async.commit_group;" ::: "memory")
#define CP_WAIT0()  asm volatile("cp.async.wait_group 0;" ::: "memory")
#define CP_WAIT1()  asm volatile("cp.async.wait_group 1;" ::: "memory")

// ---------------------------------------------------------------------------
// K0: build g_Bt[192][128]  (unchanged)
// ---------------------------------------------------------------------------
__global__ __launch_bounds__(512) void k0_bt(const float* __restrict__ wq,
                                             const float* __restrict__ wk,
                                             const float* __restrict__ wv) {
    __shared__ float s_wk[64][65];
    __shared__ float s_wq[8][64];
    int t = threadIdx.x, b = blockIdx.x;
    if (b < 16) {
        const float4* wk4 = (const float4*)wk;
#pragma unroll
        for (int i = 0; i < 2; ++i) {
            int idx = t + i * 512;
            float4 v = wk4[idx];
            int r = (idx * 4) >> 6, c = (idx * 4) & 63;
            s_wk[r][c + 0] = v.x; s_wk[r][c + 1] = v.y;
            s_wk[r][c + 2] = v.z; s_wk[r][c + 3] = v.w;
        }
        if (t < 128) {
            float4 v = ((const float4*)(wq + b * 8 * 64))[t];
            int r = (t * 4) >> 6, c = (t * 4) & 63;
            s_wq[r][c + 0] = v.x; s_wq[r][c + 1] = v.y;
            s_wq[r][c + 2] = v.z; s_wq[r][c + 3] = v.w;
        }
        __syncthreads();
        int i = t >> 6, e = t & 63;
        float s = 0.f;
#pragma unroll
        for (int f = 0; f < 64; ++f) s = fmaf(s_wq[i][f], s_wk[e][f], s);
        g_Bt[e * 128 + (b * 8 + i)] = s;
    } else {
        int j = (b - 16) * 8 + (t >> 6);
        int k = t & 63;
        g_Bt[(64 + j) * 128 + k]      = wv[k * 128 + j];
        g_Bt[(64 + j) * 128 + k + 64] = wv[(k + 64) * 128 + j];
    }
}

// ---------------------------------------------------------------------------
// K1 v2 (unchanged from 160.5us best): bf16-split HMMA, K-chunked, 512 thr.
// ---------------------------------------------------------------------------
#define KST    40                         // bf16 row stride (conflict-free)
#define K1_SMEM ((128 * KST + 192 * KST) * 2 * 2)   // 51200 bytes

__global__ __launch_bounds__(512) void k1_mma(const float* __restrict__ nodes,
                                              int N) {
    extern __shared__ __align__(16) char sm[];
    __nv_bfloat16* sAh = (__nv_bfloat16*)sm;
    __nv_bfloat16* sAl = sAh + 128 * KST;
    __nv_bfloat16* sBh = sAl + 128 * KST;
    __nv_bfloat16* sBl = sBh + 192 * KST;

    int t    = threadIdx.x;
    int wid  = t >> 5, lane = t & 31;
    int grp  = lane >> 2, tig = lane & 3;
    int wr   = wid >> 2;
    int wc   = wid & 3;
    int m0   = blockIdx.x * 128;

    float acc[2][6][4];
#pragma unroll
    for (int mt = 0; mt < 2; ++mt)
#pragma unroll
        for (int nt = 0; nt < 6; ++nt)
#pragma unroll
            for (int c = 0; c < 4; ++c) acc[mt][nt][c] = 0.f;

    const float4* nodes4 = (const float4*)nodes;
    const float4* bt4    = (const float4*)g_Bt;

    for (int ko = 0; ko < 4; ++ko) {
        __syncthreads();
#pragma unroll
        for (int i = 0; i < 2; ++i) {
            int s = t + i * 512;
            int row = s >> 3, q4 = s & 7;
            int gr = m0 + row;
            if (gr > N - 1) gr = N - 1;
            float4 v = __ldg(&nodes4[(size_t)gr * 32 + ko * 8 + q4]);
            uint32_t h0, l0, h1, l1;
            split2(v.x, v.y, h0, l0);
            split2(v.z, v.w, h1, l1);
            *(uint2*)&sAh[row * KST + q4 * 4] = make_uint2(h0, h1);
            *(uint2*)&sAl[row * KST + q4 * 4] = make_uint2(l0, l1);
        }
#pragma unroll
        for (int i = 0; i < 3; ++i) {
            int s = t + i * 512;
            int row = s >> 3, q4 = s & 7;
            float4 v = __ldg(&bt4[row * 32 + ko * 8 + q4]);
            uint32_t h0, l0, h1, l1;
            split2(v.x, v.y, h0, l0);
            split2(v.z, v.w, h1, l1);
            *(uint2*)&sBh[row * KST + q4 * 4] = make_uint2(h0, h1);
            *(uint2*)&sBl[row * KST + q4 * 4] = make_uint2(l0, l1);
        }
        __syncthreads();

#pragma unroll
        for (int kc = 0; kc < 2; ++kc) {
            int k0 = kc * 16;
#pragma unroll
            for (int tm = 0; tm < 3; ++tm) {
                const __nv_bfloat16* As = (tm == 1) ? sAl : sAh;
                const __nv_bfloat16* Bs = (tm == 2) ? sBl : sBh;

                uint32_t a[2][4], b[6][2];
#pragma unroll
                for (int mt = 0; mt < 2; ++mt) {
                    int rm = wr * 32 + mt * 16 + grp;
                    const __nv_bfloat16* p = &As[rm * KST + k0 + tig * 2];
                    a[mt][0] = *(const uint32_t*)p;
                    a[mt][1] = *(const uint32_t*)(p + 8 * KST);
                    a[mt][2] = *(const uint32_t*)(p + 8);
                    a[mt][3] = *(const uint32_t*)(p + 8 * KST + 8);
                }
#pragma unroll
                for (int nt = 0; nt < 6; ++nt) {
                    int cn = wc * 48 + nt * 8 + grp;
                    const __nv_bfloat16* p = &Bs[cn * KST + k0 + tig * 2];
                    b[nt][0] = *(const uint32_t*)p;
                    b[nt][1] = *(const uint32_t*)(p + 8);
                }
#pragma unroll
                for (int mt = 0; mt < 2; ++mt)
#pragma unroll
                    for (int nt = 0; nt < 6; ++nt)
                        MMA16816(acc[mt][nt], a[mt], b[nt]);
            }
        }
    }

#pragma unroll
    for (int mt = 0; mt < 2; ++mt) {
        int r0 = m0 + wr * 32 + mt * 16 + grp;
#pragma unroll
        for (int nt = 0; nt < 6; ++nt) {
            int col = wc * 48 + nt * 8 + tig * 2;
            float* a4 = acc[mt][nt];
            if (col < 64) {
                *(float2*)&g_q2[(size_t)r0 * 64 + col] =
                    make_float2(a4[0], a4[1]);
                *(float2*)&g_q2[(size_t)(r0 + 8) * 64 + col] =
                    make_float2(a4[2], a4[3]);
            } else {
                __half2 h0 = __floats2half2_rn(a4[0], a4[1]);
                __half2 h1 = __floats2half2_rn(a4[2], a4[3]);
                *(__half2*)&g_nv[(size_t)r0 * 128 + (col - 64)] = h0;
                *(__half2*)&g_nv[(size_t)(r0 + 8) * 128 + (col - 64)] = h1;
            }
        }
    }
}

// ---------------------------------------------------------------------------
// K2 v3: PERSISTENT grid (G blocks), each block loops nodes n = bid + i*G
// with cross-node cp.async double buffering (stage n+G while computing n).
// Inner math identical to the 160.5us version (same rel_err expected).
// ---------------------------------------------------------------------------
#define K2_GRID 1628    // 148 SMs x 11 blocks (smem-fit)

__global__ __launch_bounds__(128) void k2_persist(const float* __restrict__ edges,
                                                  const int*   __restrict__ nlist,
                                                  const float* __restrict__ inv_degree,
                                                  float*       __restrict__ out,
                                                  int N) {
    int t = threadIdx.x;
    int w = t >> 5;
    int l = t & 31;
    int bid = blockIdx.x;

    __shared__ __align__(16) float s_e[2][32][68];   // double-buffered edges
    __shared__ __align__(16) float s_q2[2][64];
    __shared__ __align__(16) int   s_idx[2][32];
    __shared__ float s_l[32];
    __shared__ __align__(16) float s_red[4][128];

    uint32_t sa_e   = (uint32_t)__cvta_generic_to_shared(&s_e[0][0][0]);
    uint32_t sa_q2  = (uint32_t)__cvta_generic_to_shared(&s_q2[0][0]);
    uint32_t sa_idx = (uint32_t)__cvta_generic_to_shared(&s_idx[0][0]);

    // issue all async copies for node n into buffer `buf`, then commit
    auto stage = [&](int buf, int n) {
        const char* esrc = (const char*)(edges + (size_t)n * 2048);
        uint32_t eb = sa_e + buf * 8704;          // 32*68*4 bytes per buffer
#pragma unroll
        for (int i = 0; i < 4; ++i) {
            int c = t + i * 128;                  // chunk 0..511
            CP_ASYNC16(eb + (c >> 4) * 272 + (c & 15) * 16, esrc + c * 16);
        }
        if (t < 16) {
            CP_ASYNC16(sa_q2 + buf * 256 + t * 16,
                       (const char*)(g_q2 + (size_t)n * 64) + t * 16);
        } else if (t < 24) {
            CP_ASYNC16(sa_idx + buf * 128 + (t - 16) * 16,
                       (const char*)(nlist + (size_t)n * 32) + (t - 16) * 16);
        }
        CP_COMMIT();
    };

    if (bid >= N) return;
    stage(0, bid);

    int buf = 0;
    for (int n = bid; n < N; n += K2_GRID, buf ^= 1) {
        int nn = n + K2_GRID;
        if (nn < N) stage(buf ^ 1, nn);
        else        CP_COMMIT();                  // keep group count uniform
        CP_WAIT1();                               // buffer `buf` ready
        float inv = __ldg(&inv_degree[n]);
        __syncthreads();

        // ---- logits: 4 threads per k, 16 features each (smem reads) ----
        {
            int k = t >> 2, q = t & 3;
            const float4* er = (const float4*)&s_e[buf][k][q * 16];
            const float4* wr = (const float4*)&s_q2[buf][q * 16];
            float p = 0.f;
#pragma unroll
            for (int i = 0; i < 4; ++i) {
                float4 e = er[i];
                float4 ww = wr[i];
                p = fmaf(e.x, ww.x, p);
                p = fmaf(e.y, ww.y, p);
                p = fmaf(e.z, ww.z, p);
                p = fmaf(e.w, ww.w, p);
            }
            p += __shfl_xor_sync(0xffffffffu, p, 1);
            p += __shfl_xor_sync(0xffffffffu, p, 2);
            if (q == 0) s_l[k] = p * inv;
        }
        __syncthreads();

        // ---- per-warp softmax over K=32 ----
        float lg = s_l[l];
        float m = lg;
#pragma unroll
        for (int o = 16; o; o >>= 1) m = fmaxf(m, __shfl_xor_sync(0xffffffffu, m, o));
        float ex = __expf(lg - m);
        float sum = ex;
#pragma unroll
        for (int o = 16; o; o >>= 1) sum += __shfl_xor_sync(0xffffffffu, sum, o);
        float bl = ex / sum;

        // ---- pruned weighted fp16 gather ----
        float4 acc = make_float4(0.f, 0.f, 0.f, 0.f);
#pragma unroll
        for (int kk = 0; kk < 8; ++kk) {
            int   ki  = w * 8 + kk;
            float bw  = __shfl_sync(0xffffffffu, bl, ki);
            if (bw >= 1e-4f) {
                int   row = s_idx[buf][ki];
                uint2 v = *(const uint2*)&g_nv[(size_t)row * 128 + l * 4];
                float2 f0 = __half22float2(*(__half2*)&v.x);
                float2 f1 = __half22float2(*(__half2*)&v.y);
                acc.x = fmaf(bw, f0.x, acc.x);
                acc.y = fmaf(bw, f0.y, acc.y);
                acc.z = fmaf(bw, f1.x, acc.z);
                acc.w = fmaf(bw, f1.y, acc.w);
            }
        }
        *(float4*)&s_red[w][l * 4] = acc;
        __syncthreads();

        // ---- cross-warp reduce + streaming store ----
        float r0 = s_red[0][t] + s_red[1][t];
        float r1 = s_red[2][t] + s_red[3][t];
        __stcs(&out[(size_t)n * 128 + t], r0 + r1);
        // loop barrier semantics: next stage() writes buf only after this
        // iteration's reads of buf completed (gather precedes last sync).
    }
}

// ---------------------------------------------------------------------------
// Inputs (metadata order): nodes f32[N,128], nlist i32[N,32], edges f32[N,32,64],
//                          inv_degree f32[N], wq f32[128,64], wk f32[64,64],
//                          wv f32[128,128]
// Output: f32[N,128]
// ---------------------------------------------------------------------------
extern "C" void kernel_launch(void* const* d_in, const int* in_sizes, int n_in,
                              void* d_out, int out_size) {
    const float* nodes      = (const float*)d_in[0];
    const int*   nlist      = (const int*)  d_in[1];
    const float* edges      = (const float*)d_in[2];
    const float* inv_degree = (const float*)d_in[3];
    const float* wq         = (const float*)d_in[4];
    const float* wk         = (const float*)d_in[5];
    const float* wv         = (const float*)d_in[6];
    float*       out        = (float*)d_out;

    int N = in_sizes[0] / FN;   // 50000

    // idempotent host-side attribute set (not enqueued; capture-safe)
    cudaFuncSetAttribute(k1_mma, cudaFuncAttributeMaxDynamicSharedMemorySize,
                         K1_SMEM);

    k0_bt<<<32, 512>>>(wq, wk, wv);
    k1_mma<<<(N + 127) / 128, 512, K1_SMEM>>>(nodes, N);
    k2_persist<<<K2_GRID, 128>>>(edges, nlist, inv_degree, out, N);
}

// round 16
// speedup vs baseline: 1.3160x; 1.3160x over previous
#include <cuda_runtime.h>
#include <cuda_fp16.h>
#include <cuda_bf16.h>
#include <cstdint>

// Problem constants (fixed by the reference: N=50000, K=32, FN=128, FE=64)
#define NMAX   50048          // 50000 padded to multiple of 128
#define FN     128
#define FE     64

// Scratch (device globals: allocation-free per harness rules)
__device__ float  g_Bt[192 * 128];        // B^T: row n<64: (wq@wk^T)[:,n]; row 64+j: wv[:,j]
__device__ float  g_q2[NMAX * 64];        // nodes @ (wq @ wk^T)   [N, FE] fp32
__device__ __half g_nv[NMAX * 128];       // nodes @ wv            [N, FN] fp16
__device__ float  g_b[NMAX * 32];         // softmax weights       [N, K]  fp32

// ---------------------------------------------------------------------------
// helpers
// ---------------------------------------------------------------------------
__device__ __forceinline__ void split2(float x, float y, uint32_t& hi, uint32_t& lo) {
    __nv_bfloat16 hx = __float2bfloat16_rn(x);
    __nv_bfloat16 hy = __float2bfloat16_rn(y);
    __nv_bfloat162 hh; hh.x = hx; hh.y = hy;
    hi = *(uint32_t*)&hh;
    __nv_bfloat162 ll = __floats2bfloat162_rn(x - __bfloat162float(hx),
                                              y - __bfloat162float(hy));
    lo = *(uint32_t*)&ll;
}

// mma.sync m16n8k16 bf16 (baseline PTX, sm_80+; compiles at compute_103)
#define MMA16816(d, a, b)                                                     \
    asm volatile(                                                             \
        "mma.sync.aligned.m16n8k16.row.col.f32.bf16.bf16.f32 "               \
        "{%0,%1,%2,%3}, {%4,%5,%6,%7}, {%8,%9}, {%0,%1,%2,%3};"              \
        : "+f"((d)[0]), "+f"((d)[1]), "+f"((d)[2]), "+f"((d)[3])              \
        : "r"((a)[0]), "r"((a)[1]), "r"((a)[2]), "r"((a)[3]),                 \
          "r"((b)[0]), "r"((b)[1]))

// cp.async (baseline PTX, sm_80+). .cg = L1-bypass 16B copy.
#define CP_ASYNC16(dst, src) \
    asm volatile("cp.async.cg.shared.global [%0], [%1], 16;" \
                 :: "r"(dst), "l"(src) : "memory")
#define CP_COMMIT() asm volatile("cp.async.commit_group;" ::: "memory")
#define CP_WAIT0()  asm volatile("cp.async.wait_group 0;" ::: "memory")

// ---------------------------------------------------------------------------
// K0: build g_Bt[192][128]  (unchanged)
// ---------------------------------------------------------------------------
__global__ __launch_bounds__(512) void k0_bt(const float* __restrict__ wq,
                                             const float* __restrict__ wk,
                                             const float* __restrict__ wv) {
    __shared__ float s_wk[64][65];
    __shared__ float s_wq[8][64];
    int t = threadIdx.x, b = blockIdx.x;
    if (b < 16) {
        const float4* wk4 = (const float4*)wk;
#pragma unroll
        for (int i = 0; i < 2; ++i) {
            int idx = t + i * 512;
            float4 v = wk4[idx];
            int r = (idx * 4) >> 6, c = (idx * 4) & 63;
            s_wk[r][c + 0] = v.x; s_wk[r][c + 1] = v.y;
            s_wk[r][c + 2] = v.z; s_wk[r][c + 3] = v.w;
        }
        if (t < 128) {
            float4 v = ((const float4*)(wq + b * 8 * 64))[t];
            int r = (t * 4) >> 6, c = (t * 4) & 63;
            s_wq[r][c + 0] = v.x; s_wq[r][c + 1] = v.y;
            s_wq[r][c + 2] = v.z; s_wq[r][c + 3] = v.w;
        }
        __syncthreads();
        int i = t >> 6, e = t & 63;
        float s = 0.f;
#pragma unroll
        for (int f = 0; f < 64; ++f) s = fmaf(s_wq[i][f], s_wk[e][f], s);
        g_Bt[e * 128 + (b * 8 + i)] = s;
    } else {
        int j = (b - 16) * 8 + (t >> 6);
        int k = t & 63;
        g_Bt[(64 + j) * 128 + k]      = wv[k * 128 + j];
        g_Bt[(64 + j) * 128 + k + 64] = wv[(k + 64) * 128 + j];
    }
}

// ---------------------------------------------------------------------------
// K1 v2 (unchanged from 160.5us best): bf16-split HMMA, K-chunked, 512 thr.
// ---------------------------------------------------------------------------
#define KST    40                         // bf16 row stride (conflict-free)
#define K1_SMEM ((128 * KST + 192 * KST) * 2 * 2)   // 51200 bytes

__global__ __launch_bounds__(512) void k1_mma(const float* __restrict__ nodes,
                                              int N) {
    extern __shared__ __align__(16) char sm[];
    __nv_bfloat16* sAh = (__nv_bfloat16*)sm;
    __nv_bfloat16* sAl = sAh + 128 * KST;
    __nv_bfloat16* sBh = sAl + 128 * KST;
    __nv_bfloat16* sBl = sBh + 192 * KST;

    int t    = threadIdx.x;
    int wid  = t >> 5, lane = t & 31;
    int grp  = lane >> 2, tig = lane & 3;
    int wr   = wid >> 2;
    int wc   = wid & 3;
    int m0   = blockIdx.x * 128;

    float acc[2][6][4];
#pragma unroll
    for (int mt = 0; mt < 2; ++mt)
#pragma unroll
        for (int nt = 0; nt < 6; ++nt)
#pragma unroll
            for (int c = 0; c < 4; ++c) acc[mt][nt][c] = 0.f;

    const float4* nodes4 = (const float4*)nodes;
    const float4* bt4    = (const float4*)g_Bt;

    for (int ko = 0; ko < 4; ++ko) {
        __syncthreads();
#pragma unroll
        for (int i = 0; i < 2; ++i) {
            int s = t + i * 512;
            int row = s >> 3, q4 = s & 7;
            int gr = m0 + row;
            if (gr > N - 1) gr = N - 1;
            float4 v = __ldg(&nodes4[(size_t)gr * 32 + ko * 8 + q4]);
            uint32_t h0, l0, h1, l1;
            split2(v.x, v.y, h0, l0);
            split2(v.z, v.w, h1, l1);
            *(uint2*)&sAh[row * KST + q4 * 4] = make_uint2(h0, h1);
            *(uint2*)&sAl[row * KST + q4 * 4] = make_uint2(l0, l1);
        }
#pragma unroll
        for (int i = 0; i < 3; ++i) {
            int s = t + i * 512;
            int row = s >> 3, q4 = s & 7;
            float4 v = __ldg(&bt4[row * 32 + ko * 8 + q4]);
            uint32_t h0, l0, h1, l1;
            split2(v.x, v.y, h0, l0);
            split2(v.z, v.w, h1, l1);
            *(uint2*)&sBh[row * KST + q4 * 4] = make_uint2(h0, h1);
            *(uint2*)&sBl[row * KST + q4 * 4] = make_uint2(l0, l1);
        }
        __syncthreads();

#pragma unroll
        for (int kc = 0; kc < 2; ++kc) {
            int k0 = kc * 16;
#pragma unroll
            for (int tm = 0; tm < 3; ++tm) {
                const __nv_bfloat16* As = (tm == 1) ? sAl : sAh;
                const __nv_bfloat16* Bs = (tm == 2) ? sBl : sBh;

                uint32_t a[2][4], b[6][2];
#pragma unroll
                for (int mt = 0; mt < 2; ++mt) {
                    int rm = wr * 32 + mt * 16 + grp;
                    const __nv_bfloat16* p = &As[rm * KST + k0 + tig * 2];
                    a[mt][0] = *(const uint32_t*)p;
                    a[mt][1] = *(const uint32_t*)(p + 8 * KST);
                    a[mt][2] = *(const uint32_t*)(p + 8);
                    a[mt][3] = *(const uint32_t*)(p + 8 * KST + 8);
                }
#pragma unroll
                for (int nt = 0; nt < 6; ++nt) {
                    int cn = wc * 48 + nt * 8 + grp;
                    const __nv_bfloat16* p = &Bs[cn * KST + k0 + tig * 2];
                    b[nt][0] = *(const uint32_t*)p;
                    b[nt][1] = *(const uint32_t*)(p + 8);
                }
#pragma unroll
                for (int mt = 0; mt < 2; ++mt)
#pragma unroll
                    for (int nt = 0; nt < 6; ++nt)
                        MMA16816(acc[mt][nt], a[mt], b[nt]);
            }
        }
    }

#pragma unroll
    for (int mt = 0; mt < 2; ++mt) {
        int r0 = m0 + wr * 32 + mt * 16 + grp;
#pragma unroll
        for (int nt = 0; nt < 6; ++nt) {
            int col = wc * 48 + nt * 8 + tig * 2;
            float* a4 = acc[mt][nt];
            if (col < 64) {
                *(float2*)&g_q2[(size_t)r0 * 64 + col] =
                    make_float2(a4[0], a4[1]);
                *(float2*)&g_q2[(size_t)(r0 + 8) * 64 + col] =
                    make_float2(a4[2], a4[3]);
            } else {
                __half2 h0 = __floats2half2_rn(a4[0], a4[1]);
                __half2 h1 = __floats2half2_rn(a4[2], a4[3]);
                *(__half2*)&g_nv[(size_t)r0 * 128 + (col - 64)] = h0;
                *(__half2*)&g_nv[(size_t)(r0 + 8) * 128 + (col - 64)] = h1;
            }
        }
    }
}

// ---------------------------------------------------------------------------
// K2a: STREAM phase. 1 node/block, 128 threads. cp.async edge stage, logit
// dot, per-warp softmax, store b[n][32] fp32. No gather -> pure DRAM stream.
// ---------------------------------------------------------------------------
__global__ __launch_bounds__(128) void k2a_logits(const float* __restrict__ edges,
                                                  const float* __restrict__ inv_degree) {
    int n = blockIdx.x;
    int t = threadIdx.x;
    int l = t & 31;

    __shared__ __align__(16) float s_e[32][68];   // padded edge rows
    __shared__ __align__(16) float s_q2[64];
    __shared__ float s_l[32];

    uint32_t sa_e  = (uint32_t)__cvta_generic_to_shared(&s_e[0][0]);
    uint32_t sa_q2 = (uint32_t)__cvta_generic_to_shared(&s_q2[0]);

    const char* esrc = (const char*)(edges + (size_t)n * 2048);
#pragma unroll
    for (int i = 0; i < 4; ++i) {
        int c = t + i * 128;            // chunk 0..511
        CP_ASYNC16(sa_e + (c >> 4) * 272 + (c & 15) * 16, esrc + c * 16);
    }
    if (t < 16) {
        CP_ASYNC16(sa_q2 + t * 16,
                   (const char*)(g_q2 + (size_t)n * 64) + t * 16);
    }
    CP_COMMIT();
    float inv = __ldg(&inv_degree[n]);
    CP_WAIT0();
    __syncthreads();

    // ---- logits: 4 threads per k, 16 features each ----
    {
        int k = t >> 2, q = t & 3;
        const float4* er = (const float4*)&s_e[k][q * 16];
        const float4* wr = (const float4*)&s_q2[q * 16];
        float p = 0.f;
#pragma unroll
        for (int i = 0; i < 4; ++i) {
            float4 e = er[i];
            float4 ww = wr[i];
            p = fmaf(e.x, ww.x, p);
            p = fmaf(e.y, ww.y, p);
            p = fmaf(e.z, ww.z, p);
            p = fmaf(e.w, ww.w, p);
        }
        p += __shfl_xor_sync(0xffffffffu, p, 1);
        p += __shfl_xor_sync(0xffffffffu, p, 2);
        if (q == 0) s_l[k] = p * inv;
    }
    __syncthreads();

    // ---- softmax in warp 0, store b ----
    if (t < 32) {
        float lg = s_l[l];
        float m = lg;
#pragma unroll
        for (int o = 16; o; o >>= 1) m = fmaxf(m, __shfl_xor_sync(0xffffffffu, m, o));
        float ex = __expf(lg - m);
        float sum = ex;
#pragma unroll
        for (int o = 16; o; o >>= 1) sum += __shfl_xor_sync(0xffffffffu, sum, o);
        __stcs(&g_b[(size_t)n * 32 + l], ex / sum);
    }
}

// ---------------------------------------------------------------------------
// K2b: GATHER phase. One WARP per node (4 nodes/block), zero smem, zero
// barriers. Lane l holds b[l]/nlist[l]; shfl broadcast per k; pruned fp16
// gather (skip b < 1e-4); float4 coalesced store. Pure L2 phase.
// ---------------------------------------------------------------------------
__global__ __launch_bounds__(128) void k2b_gather(const int* __restrict__ nlist,
                                                  float*     __restrict__ out) {
    int t = threadIdx.x;
    int w = t >> 5;
    int l = t & 31;
    int n = blockIdx.x * 4 + w;

    float bw_l  = __ldg(&g_b[(size_t)n * 32 + l]);
    int   idx_l = __ldg(&nlist[(size_t)n * 32 + l]);

    float4 acc = make_float4(0.f, 0.f, 0.f, 0.f);
#pragma unroll
    for (int kk = 0; kk < 32; ++kk) {
        float bw  = __shfl_sync(0xffffffffu, bw_l, kk);
        int   row = __shfl_sync(0xffffffffu, idx_l, kk);
        if (bw >= 1e-4f) {
            uint2 v = *(const uint2*)&g_nv[(size_t)row * 128 + l * 4];
            float2 f0 = __half22float2(*(__half2*)&v.x);
            float2 f1 = __half22float2(*(__half2*)&v.y);
            acc.x = fmaf(bw, f0.x, acc.x);
            acc.y = fmaf(bw, f0.y, acc.y);
            acc.z = fmaf(bw, f1.x, acc.z);
            acc.w = fmaf(bw, f1.y, acc.w);
        }
    }
    __stcs((float4*)&out[(size_t)n * 128 + l * 4], acc);
}

// ---------------------------------------------------------------------------
// Inputs (metadata order): nodes f32[N,128], nlist i32[N,32], edges f32[N,32,64],
//                          inv_degree f32[N], wq f32[128,64], wk f32[64,64],
//                          wv f32[128,128]
// Output: f32[N,128]
// ---------------------------------------------------------------------------
extern "C" void kernel_launch(void* const* d_in, const int* in_sizes, int n_in,
                              void* d_out, int out_size) {
    const float* nodes      = (const float*)d_in[0];
    const int*   nlist      = (const int*)  d_in[1];
    const float* edges      = (const float*)d_in[2];
    const float* inv_degree = (const float*)d_in[3];
    const float* wq         = (const float*)d_in[4];
    const float* wk         = (const float*)d_in[5];
    const float* wv         = (const float*)d_in[6];
    float*       out        = (float*)d_out;

    int N = in_sizes[0] / FN;   // 50000

    // idempotent host-side attribute set (not enqueued; capture-safe)
    cudaFuncSetAttribute(k1_mma, cudaFuncAttributeMaxDynamicSharedMemorySize,
                         K1_SMEM);

    k0_bt<<<32, 512>>>(wq, wk, wv);
    k1_mma<<<(N + 127) / 128, 512, K1_SMEM>>>(nodes, N);
    k2a_logits<<<N, 128>>>(edges, inv_degree);
    k2b_gather<<<N / 4, 128>>>(nlist, out);
}